// round 8
// baseline (speedup 1.0000x reference)
#include <cuda_runtime.h>
#include <cstdint>

// Correlation1D via warp-level tf32 mma.sync band-GEMM.
// Persistent CTAs, cp.async 2-stage pipeline that runs CONTINUOUSLY across
// row boundaries (epilogue overlaps the next row's loads).
// out[b,d,h,w] = (1/256) * sum_c in1[b,c,h,w] * in2[b,c,h,w+d-40], d in [0,81)
// Per row (b,h): D[w, sj] = sum_c in1[c,w] * in2[c, sj-40], sj = w+d in [0,272).
// 12 warps: warp mt owns w0=16*mt, n-tiles sj in [w0, w0+96) -> 12 tiles of 8.
// f32 staged raw via cp.async (zero-fill OOB); RNA->tf32 applied after LDS.

#define BB 8
#define CC 256
#define HH 96
#define WW 192
#define DD 81
#define HW (HH*WW)
#define CHW ((size_t)CC*(size_t)HW)
#define NROWS (BB*HH)         // 768

#define NCTA 296              // 2 per SM * 148 SMs
#define NTHR 384
#define KC 16                 // k-rows per chunk
#define NKC (CC/KC)           // 16 chunks per row
#define SAW 200               // A row stride (words): conflict-free
#define SBW 280               // B row stride (words): conflict-free
#define SB_OFF (KC*SAW)       // 3200 words
#define STG_W (KC*SAW + KC*SBW)   // 7680 words per stage
#define BUF_W (32*SAW)            // 6400 words epilogue buffer
#define SMEM_WORDS (2*STG_W + BUF_W)   // 21760 words = 87040 B
#define SMEM_BYTES (SMEM_WORDS*4)

__device__ __forceinline__ void cp16(uint32_t daddr, const float* src, uint32_t sz) {
    asm volatile("cp.async.cg.shared.global [%0], [%1], 16, %2;"
                 :: "r"(daddr), "l"(src), "r"(sz));
}

__device__ __forceinline__ uint32_t f2tf32(uint32_t raw) {
    uint32_t u;
    asm("cvt.rna.tf32.f32 %0, %1;" : "=r"(u) : "f"(__uint_as_float(raw)));
    return u;
}

__device__ __forceinline__ void mma_tf32(float (&d)[4], const uint32_t (&a)[4],
                                         uint32_t b0, uint32_t b1) {
    asm volatile(
        "mma.sync.aligned.m16n8k8.row.col.f32.tf32.tf32.f32 "
        "{%0,%1,%2,%3}, {%4,%5,%6,%7}, {%8,%9}, {%0,%1,%2,%3};"
        : "+f"(d[0]), "+f"(d[1]), "+f"(d[2]), "+f"(d[3])
        : "r"(a[0]), "r"(a[1]), "r"(a[2]), "r"(a[3]), "r"(b0), "r"(b1));
}

extern __shared__ uint32_t smem[];

__global__ __launch_bounds__(NTHR, 2)
void corr_hmma6(const float* __restrict__ in1, const float* __restrict__ in2,
                float* __restrict__ out) {
    const int bx   = blockIdx.x;
    const int tid  = threadIdx.x;
    const int wid  = tid >> 5;
    const int lane = tid & 31;
    const int g    = lane >> 2;
    const int l4   = lane & 3;
    const int w0   = wid * 16;

    const int nrows   = (NROWS - bx + NCTA - 1) / NCTA;   // 2 or 3
    const int nchunks = nrows * NKC;

    uint32_t smem_u32;
    {
        uint32_t a;
        asm("{ .reg .u64 t; cvta.to.shared.u64 t, %1; cvt.u32.u64 %0, t; }"
            : "=r"(a) : "l"((const void*)smem));
        smem_u32 = a;
    }

    // per-thread cp.async assignments (2 A ops + up to 3 B ops per thread)
    const int a0r = tid / 48,         a0s = tid % 48;
    const int a1r = (tid + 384) / 48, a1s = (tid + 384) % 48;
    const int b0r = tid / 68,         b0j = tid % 68;
    const int b1r = (tid + 384) / 68, b1j = (tid + 384) % 68;
    const int b2r = (tid + 768) / 68, b2j = (tid + 768) % 68;
    const bool hasB2 = (tid + 768 < KC * 68);
    const uint32_t b0sz = (b0j >= 10 && b0j < 58) ? 16u : 0u;
    const uint32_t b1sz = (b1j >= 10 && b1j < 58) ? 16u : 0u;
    const uint32_t b2sz = (b2j >= 10 && b2j < 58) ? 16u : 0u;

    float acc[12][4];
#pragma unroll
    for (int nt = 0; nt < 12; nt++)
#pragma unroll
        for (int ci = 0; ci < 4; ci++) acc[nt][ci] = 0.f;

    // ---- issue chunk g of this CTA's global chunk sequence ----
    auto issue = [&](int gc) {
        if (gc < nchunks) {
            const int rr = bx + (gc >> 4) * NCTA;          // row index
            const int kc = gc & 15;
            const size_t rbase = (size_t)(rr / HH) * CHW + (size_t)(rr % HH) * WW
                               + (size_t)kc * KC * HW;
            const float* p1 = in1 + rbase;
            const float* p2 = in2 + rbase;
            const uint32_t sb = smem_u32 + (uint32_t)(gc & 1) * STG_W * 4;
            cp16(sb + (a0r * SAW + a0s * 4) * 4, p1 + (size_t)a0r * HW + a0s * 4, 16u);
            cp16(sb + (a1r * SAW + a1s * 4) * 4, p1 + (size_t)a1r * HW + a1s * 4, 16u);
            cp16(sb + (SB_OFF + b0r * SBW + b0j * 4) * 4, p2 + (size_t)b0r * HW + b0j * 4 - 40, b0sz);
            cp16(sb + (SB_OFF + b1r * SBW + b1j * 4) * 4, p2 + (size_t)b1r * HW + b1j * 4 - 40, b1sz);
            if (hasB2)
                cp16(sb + (SB_OFF + b2r * SBW + b2j * 4) * 4, p2 + (size_t)b2r * HW + b2j * 4 - 40, b2sz);
        }
        asm volatile("cp.async.commit_group;" ::: "memory");  // always commit (tail invariant)
    };

    issue(0);
    issue(1);

    float* buf = reinterpret_cast<float*>(smem + 2 * STG_W);  // dedicated epilogue buffer

    for (int gc = 0; gc < nchunks; gc++) {
        asm volatile("cp.async.wait_group 1;" ::: "memory");
        __syncthreads();
        const uint32_t* sb = smem + (gc & 1) * STG_W;

#pragma unroll
        for (int ks = 0; ks < KC; ks += 8) {
            uint32_t a[4];
            a[0] = f2tf32(sb[(ks + l4) * SAW + w0 + g]);
            a[1] = f2tf32(sb[(ks + l4) * SAW + w0 + g + 8]);
            a[2] = f2tf32(sb[(ks + l4 + 4) * SAW + w0 + g]);
            a[3] = f2tf32(sb[(ks + l4 + 4) * SAW + w0 + g + 8]);
#pragma unroll
            for (int nt = 0; nt < 12; nt++) {
                const int bc = w0 + 8 * nt + g;
                const uint32_t bb0 = f2tf32(sb[SB_OFF + (ks + l4) * SBW + bc]);
                const uint32_t bb1 = f2tf32(sb[SB_OFF + (ks + l4 + 4) * SBW + bc]);
                mma_tf32(acc[nt], a, bb0, bb1);
            }
        }
        __syncthreads();     // stage reads done before re-fill
        issue(gc + 2);       // keeps streaming across the row boundary

        // ---- row finished: epilogue overlapped with next row's loads ----
        if ((gc & 15) == 15) {
            const int rr = bx + (gc >> 4) * NCTA;
            float* pout = out + (size_t)(rr / HH) * DD * HW + (size_t)(rr % HH) * WW;
#pragma unroll
            for (int chunk = 0; chunk < 3; chunk++) {
                const int d0 = chunk * 32;
                if (chunk) __syncthreads();
#pragma unroll
                for (int nt = 0; nt < 12; nt++) {
#pragma unroll
                    for (int ci = 0; ci < 4; ci++) {
                        const int wp = w0 + g + ((ci & 2) ? 8 : 0);
                        const int sj = w0 + 8 * nt + 2 * l4 + (ci & 1);
                        const int d  = sj - wp;
                        if (d >= d0 && d < d0 + 32 && d < DD)
                            buf[(d - d0) * SAW + wp] = acc[nt][ci] * (1.0f / 256.0f);
                    }
                }
                __syncthreads();
                const int dmax = (DD - d0 < 32) ? (DD - d0) : 32;
                for (int i = tid; i < dmax * 48; i += NTHR) {
                    const int dd = i / 48;
                    const int v  = i - dd * 48;
                    *reinterpret_cast<float4*>(pout + (size_t)(d0 + dd) * HW + v * 4) =
                        *reinterpret_cast<float4*>(&buf[dd * SAW + v * 4]);
                }
            }
            // reset accumulators for the next row
#pragma unroll
            for (int nt = 0; nt < 12; nt++)
#pragma unroll
                for (int ci = 0; ci < 4; ci++) acc[nt][ci] = 0.f;
        }
    }
}

extern "C" void kernel_launch(void* const* d_in, const int* in_sizes, int n_in,
                              void* d_out, int out_size) {
    const float* in1 = (const float*)d_in[0];
    const float* in2 = (const float*)d_in[1];
    float* out = (float*)d_out;

    cudaFuncSetAttribute(corr_hmma6, cudaFuncAttributeMaxDynamicSharedMemorySize, SMEM_BYTES);
    corr_hmma6<<<NCTA, NTHR, SMEM_BYTES>>>(in1, in2, out);
}

// round 9
// speedup vs baseline: 1.4286x; 1.4286x over previous
#include <cuda_runtime.h>
#include <cstdint>

// Correlation1D via warp-level tf32 mma.sync band-GEMM, cp.async 3-stage pipeline.
// out[b,d,h,w] = (1/256) * sum_c in1[b,c,h,w] * in2[b,c,h,w+d-40], d in [0,81)
// Per CTA (b,h): D[w, sj] = sum_c in1[c,w] * in2[c, sj-40], sj = w+d in [0,272).
// 12 warps: warp mt owns w0=16*mt, n-tiles sj in [w0, w0+96) -> 12 tiles of 8.
// f32 staged raw via cp.async (zero-fill OOB); RNA->tf32 applied to fragments after LDS.
// Always-commit empty tail groups keep the wait_group counting invariant.

#define BB 8
#define CC 256
#define HH 96
#define WW 192
#define DD 81
#define HW (HH*WW)
#define CHW ((size_t)CC*(size_t)HW)

#define NTHR 384
#define KC 16                 // k-rows per chunk
#define NKC (CC/KC)           // 16 chunks
#define NSTG 3                // pipeline stages
#define SAW 200               // A row stride (words): conflict-free
#define SBW 280               // B row stride (words): conflict-free
#define SB_OFF (KC*SAW)       // 3200 words
#define STG_W (KC*SAW + KC*SBW)     // 7680 words per stage
#define SMEM_BYTES (NSTG*STG_W*4)   // 92160

__device__ __forceinline__ void cp16(uint32_t daddr, const float* src, uint32_t sz) {
    asm volatile("cp.async.cg.shared.global [%0], [%1], 16, %2;"
                 :: "r"(daddr), "l"(src), "r"(sz));
}

__device__ __forceinline__ uint32_t f2tf32(uint32_t raw) {
    uint32_t u;
    asm("cvt.rna.tf32.f32 %0, %1;" : "=r"(u) : "f"(__uint_as_float(raw)));
    return u;
}

__device__ __forceinline__ void mma_tf32(float (&d)[4], const uint32_t (&a)[4],
                                         uint32_t b0, uint32_t b1) {
    asm volatile(
        "mma.sync.aligned.m16n8k8.row.col.f32.tf32.tf32.f32 "
        "{%0,%1,%2,%3}, {%4,%5,%6,%7}, {%8,%9}, {%0,%1,%2,%3};"
        : "+f"(d[0]), "+f"(d[1]), "+f"(d[2]), "+f"(d[3])
        : "r"(a[0]), "r"(a[1]), "r"(a[2]), "r"(a[3]), "r"(b0), "r"(b1));
}

extern __shared__ uint32_t smem[];

__global__ __launch_bounds__(NTHR, 2)
void corr_hmma7(const float* __restrict__ in1, const float* __restrict__ in2,
                float* __restrict__ out) {
    const int h    = blockIdx.x;
    const int b    = blockIdx.y;
    const int tid  = threadIdx.x;
    const int wid  = tid >> 5;
    const int lane = tid & 31;
    const int g    = lane >> 2;
    const int l4   = lane & 3;
    const int w0   = wid * 16;

    const float* p1 = in1 + (size_t)b * CHW + (size_t)h * WW;
    const float* p2 = in2 + (size_t)b * CHW + (size_t)h * WW;
    float* pout = out + (size_t)b * DD * HW + (size_t)h * WW;

    uint32_t smem_u32;
    {
        uint32_t a;
        asm("{ .reg .u64 t; cvta.to.shared.u64 t, %1; cvt.u32.u64 %0, t; }"
            : "=r"(a) : "l"((const void*)smem));
        smem_u32 = a;
    }

    // per-thread cp.async assignments (2 A ops + up to 3 B ops per thread)
    const int a0r = tid / 48,         a0s = tid % 48;
    const int a1r = (tid + 384) / 48, a1s = (tid + 384) % 48;
    const int b0r = tid / 68,         b0j = tid % 68;
    const int b1r = (tid + 384) / 68, b1j = (tid + 384) % 68;
    const int b2r = (tid + 768) / 68, b2j = (tid + 768) % 68;
    const bool hasB2 = (tid + 768 < KC * 68);
    const uint32_t b0sz = (b0j >= 10 && b0j < 58) ? 16u : 0u;
    const uint32_t b1sz = (b1j >= 10 && b1j < 58) ? 16u : 0u;
    const uint32_t b2sz = (b2j >= 10 && b2j < 58) ? 16u : 0u;

    float acc[12][4];
#pragma unroll
    for (int nt = 0; nt < 12; nt++)
#pragma unroll
        for (int ci = 0; ci < 4; ci++) acc[nt][ci] = 0.f;

    auto issue = [&](int kc, int st) {
        if (kc < NKC) {
            const uint32_t sb = smem_u32 + (uint32_t)st * STG_W * 4;
            const size_t ko = (size_t)kc * KC * HW;
            cp16(sb + (a0r * SAW + a0s * 4) * 4, p1 + ko + (size_t)a0r * HW + a0s * 4, 16u);
            cp16(sb + (a1r * SAW + a1s * 4) * 4, p1 + ko + (size_t)a1r * HW + a1s * 4, 16u);
            cp16(sb + (SB_OFF + b0r * SBW + b0j * 4) * 4, p2 + ko + (size_t)b0r * HW + b0j * 4 - 40, b0sz);
            cp16(sb + (SB_OFF + b1r * SBW + b1j * 4) * 4, p2 + ko + (size_t)b1r * HW + b1j * 4 - 40, b1sz);
            if (hasB2)
                cp16(sb + (SB_OFF + b2r * SBW + b2j * 4) * 4, p2 + ko + (size_t)b2r * HW + b2j * 4 - 40, b2sz);
        }
        asm volatile("cp.async.commit_group;" ::: "memory");  // always commit (tail invariant)
    };

    issue(0, 0);
    issue(1, 1);
    issue(2, 2);

    int st = 0;   // stage of chunk kc
    for (int kc = 0; kc < NKC; kc++) {
        asm volatile("cp.async.wait_group 2;" ::: "memory");
        __syncthreads();
        const uint32_t* sb = smem + st * STG_W;

#pragma unroll
        for (int ks = 0; ks < KC; ks += 8) {
            uint32_t a[4];
            a[0] = f2tf32(sb[(ks + l4) * SAW + w0 + g]);
            a[1] = f2tf32(sb[(ks + l4) * SAW + w0 + g + 8]);
            a[2] = f2tf32(sb[(ks + l4 + 4) * SAW + w0 + g]);
            a[3] = f2tf32(sb[(ks + l4 + 4) * SAW + w0 + g + 8]);
#pragma unroll
            for (int nt = 0; nt < 12; nt++) {
                const int bc = w0 + 8 * nt + g;
                const uint32_t bb0 = f2tf32(sb[SB_OFF + (ks + l4) * SBW + bc]);
                const uint32_t bb1 = f2tf32(sb[SB_OFF + (ks + l4 + 4) * SBW + bc]);
                mma_tf32(acc[nt], a, bb0, bb1);
            }
        }
        __syncthreads();          // all reads of this stage done before re-filling it
        issue(kc + NSTG, st);     // refill the stage just consumed
        st = (st + 1 == NSTG) ? 0 : st + 1;
    }

    // ---- epilogue: diagonal extract d = sj - wp, coalesced float4 stores ----
    float* buf = reinterpret_cast<float*>(smem);   // [32][SAW] floats (aliases stage 0)
#pragma unroll
    for (int chunk = 0; chunk < 3; chunk++) {
        const int d0 = chunk * 32;
        if (chunk) __syncthreads();
#pragma unroll
        for (int nt = 0; nt < 12; nt++) {
#pragma unroll
            for (int ci = 0; ci < 4; ci++) {
                const int wp = w0 + g + ((ci & 2) ? 8 : 0);
                const int sj = w0 + 8 * nt + 2 * l4 + (ci & 1);
                const int d  = sj - wp;
                if (d >= d0 && d < d0 + 32 && d < DD)
                    buf[(d - d0) * SAW + wp] = acc[nt][ci] * (1.0f / 256.0f);
            }
        }
        __syncthreads();
        const int dmax = (DD - d0 < 32) ? (DD - d0) : 32;
        for (int i = tid; i < dmax * 48; i += NTHR) {
            const int dd = i / 48;
            const int v  = i - dd * 48;
            *reinterpret_cast<float4*>(pout + (size_t)(d0 + dd) * HW + v * 4) =
                *reinterpret_cast<float4*>(&buf[dd * SAW + v * 4]);
        }
    }
}

extern "C" void kernel_launch(void* const* d_in, const int* in_sizes, int n_in,
                              void* d_out, int out_size) {
    const float* in1 = (const float*)d_in[0];
    const float* in2 = (const float*)d_in[1];
    float* out = (float*)d_out;

    cudaFuncSetAttribute(corr_hmma7, cudaFuncAttributeMaxDynamicSharedMemorySize, SMEM_BYTES);
    dim3 grid(HH, BB);   // 768 CTAs x 384 threads
    corr_hmma7<<<grid, NTHR, SMEM_BYTES>>>(in1, in2, out);
}